// round 2
// baseline (speedup 1.0000x reference)
#include <cuda_runtime.h>
#include <cstdint>

#define HIDDEN 128
#define FEAT   512          // 4 * HIDDEN contiguous floats per node
#define MAX_NODES 12000

// Scratch: aggregated raw features per destination node (zeroed each launch).
__device__ float g_agg[(size_t)MAX_NODES * FEAT];
// 1 if edge_index buffer is int64, 0 if int32.
__device__ int g_idx64;

// ---------------------------------------------------------------------------
// Phase 0: zero the aggregation scratch
// ---------------------------------------------------------------------------
__global__ void zero_kernel(int n4) {
    int i = blockIdx.x * blockDim.x + threadIdx.x;
    if (i < n4) reinterpret_cast<float4*>(g_agg)[i] = make_float4(0.f, 0.f, 0.f, 0.f);
}

// ---------------------------------------------------------------------------
// Phase 0b: detect edge_index dtype (int64 vs int32) from data
// Reads first 64 words as int64; true int64 indices are all in [0, n).
// int32 data misread as int64 is >= 2^32 with prob ~1 - 1e-4 per word.
// ---------------------------------------------------------------------------
__global__ void detect_kernel(const long long* __restrict__ ei, long long n) {
    __shared__ int ok;
    if (threadIdx.x == 0) ok = 1;
    __syncthreads();
    long long v = ei[threadIdx.x];
    if (v < 0 || v >= n) ok = 0;   // benign race, all writers write 0
    __syncthreads();
    if (threadIdx.x == 0) g_idx64 = ok;
}

// ---------------------------------------------------------------------------
// Phase 1: edge scatter.  One warp per edge: gather x[col][0:512],
// vector-atomic-add into g_agg[row][0:512].
// ---------------------------------------------------------------------------
__global__ void scatter_kernel(const float* __restrict__ x,
                               const void* __restrict__ ei,
                               int E) {
    int gw   = (blockIdx.x * blockDim.x + threadIdx.x) >> 5;
    int lane = threadIdx.x & 31;
    if (gw >= E) return;

    long long row, col;
    if (g_idx64) {
        const long long* e64 = (const long long*)ei;
        row = e64[gw];
        col = e64[(size_t)E + gw];
    } else {
        const int* e32 = (const int*)ei;
        row = e32[gw];
        col = e32[(size_t)E + gw];
    }

    const float4* src = (const float4*)(x + (size_t)col * FEAT);
    float*        dst = g_agg + (size_t)row * FEAT;

#pragma unroll
    for (int i = 0; i < 4; ++i) {
        float4 v = src[lane + 32 * i];
        float* p = dst + (size_t)(lane + 32 * i) * 4;
        asm volatile("red.global.add.v4.f32 [%0], {%1, %2, %3, %4};"
                     :: "l"(p), "f"(v.x), "f"(v.y), "f"(v.z), "f"(v.w)
                     : "memory");
    }
}

// ---------------------------------------------------------------------------
// Phase 2: fused output GEMM.
// Grid: (ceil(n/64), 4).  blockIdx.y == 0 -> scalar slice (out cols 0:128):
//     out = scalar @ Wsroot.T + agg_s @ Wsrel.T + bias          (K = 2*128)
// blockIdx.y == y in 1..3 -> vector slice (out cols 128y : 128y+128):
//     out = vector @ Wvroot.T + agg_v @ Wvrel.T                 (K = 2*384)
// BM=64, BN=128, BK=16, 256 threads, 8x4 register microtile.
// ---------------------------------------------------------------------------
__global__ __launch_bounds__(256)
void gemm_kernel(const float* __restrict__ x,
                 const float* __restrict__ Wsrel,
                 const float* __restrict__ Wsroot,
                 const float* __restrict__ bias,
                 const float* __restrict__ Wvrel,
                 const float* __restrict__ Wvroot,
                 float* __restrict__ out, int n) {
    __shared__ float As[16][68];    // [k][m], padded
    __shared__ float Bs[16][132];   // [k][j], padded

    const int by  = blockIdx.y;
    const int m0  = blockIdx.x * 64;
    const int tid = threadIdx.x;
    const int tx  = tid & 31;       // output col group (4 cols each)
    const int ty  = tid >> 5;       // output row group (8 rows each)

    int aoff, K, ldb;
    const float* B0;
    const float* B1;
    if (by == 0) {
        aoff = 0;  K = 128; ldb = 128;
        B0 = Wsroot;
        B1 = Wsrel;
    } else {
        aoff = 128; K = 384; ldb = 384;
        B0 = Wvroot + (size_t)(by - 1) * 128 * 384;
        B1 = Wvrel  + (size_t)(by - 1) * 128 * 384;
    }

    float acc[8][4];
#pragma unroll
    for (int i = 0; i < 8; ++i)
#pragma unroll
        for (int j = 0; j < 4; ++j) acc[i][j] = 0.f;

    const int arow = tid >> 2;          // 0..63
    const int kc   = (tid & 3) * 4;     // 0,4,8,12

#pragma unroll 1
    for (int p = 0; p < 2; ++p) {
        const float* Abase = (p == 0 ? x : g_agg) + aoff;
        const float* Bbase = (p == 0 ? B0 : B1);

#pragma unroll 1
        for (int kt = 0; kt < K; kt += 16) {
            // --- load A tile (64 x 16), transposed store ---
            float4 av = make_float4(0.f, 0.f, 0.f, 0.f);
            int node = m0 + arow;
            if (node < n)
                av = *(const float4*)(Abase + (size_t)node * FEAT + kt + kc);
            As[kc + 0][arow] = av.x;
            As[kc + 1][arow] = av.y;
            As[kc + 2][arow] = av.z;
            As[kc + 3][arow] = av.w;

            // --- load B tile (128 x 16), transposed store ---
#pragma unroll
            for (int r = 0; r < 2; ++r) {
                int j = arow + 64 * r;
                float4 bv = *(const float4*)(Bbase + (size_t)j * ldb + kt + kc);
                Bs[kc + 0][j] = bv.x;
                Bs[kc + 1][j] = bv.y;
                Bs[kc + 2][j] = bv.z;
                Bs[kc + 3][j] = bv.w;
            }
            __syncthreads();

            // --- compute ---
#pragma unroll
            for (int kk = 0; kk < 16; ++kk) {
                const float* ar = &As[kk][ty * 8];
                float4 a0 = *(const float4*)(ar);
                float4 a1 = *(const float4*)(ar + 4);
                float4 b  = *(const float4*)&Bs[kk][tx * 4];
                float am[8] = {a0.x, a0.y, a0.z, a0.w, a1.x, a1.y, a1.z, a1.w};
                float bm[4] = {b.x, b.y, b.z, b.w};
#pragma unroll
                for (int i = 0; i < 8; ++i)
#pragma unroll
                    for (int j = 0; j < 4; ++j)
                        acc[i][j] += am[i] * bm[j];
            }
            __syncthreads();
        }
    }

    // --- epilogue ---
    const int jn = tx * 4;
    float4 bb = make_float4(0.f, 0.f, 0.f, 0.f);
    if (by == 0) bb = *(const float4*)(bias + jn);

#pragma unroll
    for (int i = 0; i < 8; ++i) {
        int node = m0 + ty * 8 + i;
        if (node < n) {
            float4 r;
            r.x = acc[i][0] + bb.x;
            r.y = acc[i][1] + bb.y;
            r.z = acc[i][2] + bb.z;
            r.w = acc[i][3] + bb.w;
            *(float4*)(out + (size_t)node * FEAT + by * 128 + jn) = r;
        }
    }
}

// ---------------------------------------------------------------------------
extern "C" void kernel_launch(void* const* d_in, const int* in_sizes, int n_in,
                              void* d_out, int out_size) {
    const float* x       = (const float*)d_in[0];
    const void*  ei      = d_in[1];
    const float* Wsrel   = (const float*)d_in[2];
    const float* Wsroot  = (const float*)d_in[3];
    const float* bs      = (const float*)d_in[4];
    const float* Wvrel   = (const float*)d_in[5];
    const float* Wvroot  = (const float*)d_in[6];
    float*       out     = (float*)d_out;

    const int n = in_sizes[0] / FEAT;        // 10000
    const int E = in_sizes[1] / 2;           // 160000 (count is 2*E for either dtype)

    // Phase 0: zero scratch
    const int n4 = n * FEAT / 4;
    zero_kernel<<<(n4 + 255) / 256, 256>>>(n4);

    // Phase 0b: dtype sniff
    detect_kernel<<<1, 64>>>((const long long*)ei, (long long)n);

    // Phase 1: edge scatter (1 warp / edge)
    const int warps  = E;
    const int blocks = (warps * 32 + 255) / 256;
    scatter_kernel<<<blocks, 256>>>(x, ei, E);

    // Phase 2: fused GEMM
    dim3 grid((n + 63) / 64, 4);
    gemm_kernel<<<grid, 256>>>(x, Wsrel, Wsroot, bs, Wvrel, Wvroot, out, n);
}

// round 4
// speedup vs baseline: 1.8973x; 1.8973x over previous
#include <cuda_runtime.h>
#include <cstdint>

#define HIDDEN 128
#define FEAT   512
#define MAX_NODES 12000

// Scratch: aggregated raw features per destination node.
__device__ float g_agg[(size_t)MAX_NODES * FEAT];
__device__ int g_idx64;

// ---------------------------------------------------------------------------
// Phase 0: zero aggregation scratch
// ---------------------------------------------------------------------------
__global__ void zero_kernel(int n4) {
    int i = blockIdx.x * blockDim.x + threadIdx.x;
    if (i < n4) reinterpret_cast<float4*>(g_agg)[i] = make_float4(0.f, 0.f, 0.f, 0.f);
}

// Phase 0b: detect edge_index dtype (int64 vs int32) from data
__global__ void detect_kernel(const long long* __restrict__ ei, long long n) {
    __shared__ int ok;
    if (threadIdx.x == 0) ok = 1;
    __syncthreads();
    long long v = ei[threadIdx.x];
    if (v < 0 || v >= n) ok = 0;
    __syncthreads();
    if (threadIdx.x == 0) g_idx64 = ok;
}

// ---------------------------------------------------------------------------
// Phase 1: edge scatter (1 warp/edge, vector atomics into L2-resident scratch)
// ---------------------------------------------------------------------------
__global__ void scatter_kernel(const float* __restrict__ x,
                               const void* __restrict__ ei, int E) {
    int gw   = (blockIdx.x * blockDim.x + threadIdx.x) >> 5;
    int lane = threadIdx.x & 31;
    if (gw >= E) return;

    long long row, col;
    if (g_idx64) {
        const long long* e64 = (const long long*)ei;
        row = e64[gw];
        col = e64[(size_t)E + gw];
    } else {
        const int* e32 = (const int*)ei;
        row = e32[gw];
        col = e32[(size_t)E + gw];
    }

    const float4* src = (const float4*)(x + (size_t)col * FEAT);
    float*        dst = g_agg + (size_t)row * FEAT;

#pragma unroll
    for (int i = 0; i < 4; ++i) {
        float4 v = src[lane + 32 * i];
        float* p = dst + (size_t)(lane + 32 * i) * 4;
        asm volatile("red.global.add.v4.f32 [%0], {%1, %2, %3, %4};"
                     :: "l"(p), "f"(v.x), "f"(v.y), "f"(v.z), "f"(v.w)
                     : "memory");
    }
}

// ---------------------------------------------------------------------------
// Phase 2: warp-level tf32 mma.sync GEMM.
// Per CTA: 128 nodes x 128 out-cols.  Grid (ceil(n/128), 4).
//   by==0: out_s = scalar@Wsroot.T + agg_s@Wsrel.T + bias   (K=128+128)
//   by>=1: out_v = vector@Wvroot.T + agg_v@Wvrel.T          (K=384+384)
// 256 threads = 8 warps (4x2); warp tile 32x64 = 2x8 m16n8k8 subtiles.
// smem tiles stride-36 padded -> conflict-free fragment LDS.
// ---------------------------------------------------------------------------
#define SAS 36   // smem row stride (floats)

#define MMA_TF32(c, a, b)                                                   \
    asm volatile("mma.sync.aligned.m16n8k8.row.col.f32.tf32.tf32.f32 "      \
                 "{%0,%1,%2,%3}, {%4,%5,%6,%7}, {%8,%9}, {%0,%1,%2,%3};"    \
                 : "+f"((c)[0]), "+f"((c)[1]), "+f"((c)[2]), "+f"((c)[3])   \
                 : "r"((a)[0]), "r"((a)[1]), "r"((a)[2]), "r"((a)[3]),      \
                   "r"((b)[0]), "r"((b)[1]))

__device__ __forceinline__ uint32_t f2tf32(float v) {
    uint32_t r;
    asm("cvt.rna.tf32.f32 %0, %1;" : "=r"(r) : "f"(v));
    return r;
}

__global__ __launch_bounds__(256, 2)
void mma_gemm_kernel(const float* __restrict__ x,
                     const float* __restrict__ Wsrel,
                     const float* __restrict__ Wsroot,
                     const float* __restrict__ bias,
                     const float* __restrict__ Wvrel,
                     const float* __restrict__ Wvroot,
                     float* __restrict__ out, int n) {
    __shared__ uint32_t As[128 * SAS];
    __shared__ uint32_t Bs[128 * SAS];
    __shared__ float sbias[128];

    const int tid  = threadIdx.x;
    const int wid  = tid >> 5;
    const int lane = tid & 31;
    const int gid  = lane >> 2;      // 0..7
    const int tig  = lane & 3;       // 0..3
    const int wm   = wid >> 1;       // 0..3 (m-warp)
    const int wn   = wid & 1;        // 0..1 (n-warp)
    const int by   = blockIdx.y;
    const int m0   = blockIdx.x * 128;

    int Khalf, ldb, aoff;
    const float* B0;
    const float* B1;
    if (by == 0) {
        Khalf = 128; ldb = 128; aoff = 0;
        B0 = Wsroot; B1 = Wsrel;
    } else {
        Khalf = 384; ldb = 384; aoff = 128;
        B0 = Wvroot + (size_t)(by - 1) * 128 * 384;
        B1 = Wvrel  + (size_t)(by - 1) * 128 * 384;
    }
    const int C  = (2 * Khalf) / 32;   // 8 or 24 K-chunks
    const int Ch = C / 2;

    if (tid < 128) sbias[tid] = (by == 0) ? bias[tid] : 0.f;

    float acc[2][8][4];
#pragma unroll
    for (int mt = 0; mt < 2; ++mt)
#pragma unroll
        for (int nt = 0; nt < 8; ++nt)
#pragma unroll
            for (int j = 0; j < 4; ++j) acc[mt][nt][j] = 0.f;

    // tile-loader mapping: 2 threads per 32-float row
    const int lrow  = tid >> 1;          // 0..127
    const int lcol0 = (tid & 1) * 16;    // 0 or 16

#pragma unroll 1
    for (int it = 0; it < C; ++it) {
        const int pass = (it >= Ch);
        const int kt   = (it - pass * Ch) * 32;

        if (it > 0) __syncthreads();     // previous tile fully consumed

        // ---- A tile: 128 nodes x 32 K-floats ----
        {
            const float* Ab = (pass ? (const float*)g_agg : x) + aoff;
            const int node  = m0 + lrow;
            const bool ok   = pass ? true : (node < n);
            const float4* src = (const float4*)(Ab + (size_t)node * FEAT + kt + lcol0);
            uint32_t* dst = &As[lrow * SAS + lcol0];
#pragma unroll
            for (int i = 0; i < 4; ++i) {
                float4 v = ok ? src[i] : make_float4(0.f, 0.f, 0.f, 0.f);
                dst[4 * i + 0] = f2tf32(v.x);
                dst[4 * i + 1] = f2tf32(v.y);
                dst[4 * i + 2] = f2tf32(v.z);
                dst[4 * i + 3] = f2tf32(v.w);
            }
        }
        // ---- B tile: 128 out-cols x 32 K-floats (row-major W slice) ----
        {
            const float* Bb = pass ? B1 : B0;
            const float4* src = (const float4*)(Bb + (size_t)lrow * ldb + kt + lcol0);
            uint32_t* dst = &Bs[lrow * SAS + lcol0];
#pragma unroll
            for (int i = 0; i < 4; ++i) {
                float4 v = src[i];
                dst[4 * i + 0] = f2tf32(v.x);
                dst[4 * i + 1] = f2tf32(v.y);
                dst[4 * i + 2] = f2tf32(v.z);
                dst[4 * i + 3] = f2tf32(v.w);
            }
        }
        __syncthreads();

        // ---- compute: 4 K=8 steps ----
#pragma unroll
        for (int k8 = 0; k8 < 4; ++k8) {
            const int kc = k8 * 8 + tig;
            uint32_t a[2][4], b[8][2];
#pragma unroll
            for (int mt = 0; mt < 2; ++mt) {
                const int r = wm * 32 + mt * 16 + gid;
                a[mt][0] = As[r * SAS + kc];
                a[mt][1] = As[(r + 8) * SAS + kc];
                a[mt][2] = As[r * SAS + kc + 4];
                a[mt][3] = As[(r + 8) * SAS + kc + 4];
            }
#pragma unroll
            for (int nt = 0; nt < 8; ++nt) {
                const int cidx = wn * 64 + nt * 8 + gid;
                b[nt][0] = Bs[cidx * SAS + kc];
                b[nt][1] = Bs[cidx * SAS + kc + 4];
            }
#pragma unroll
            for (int mt = 0; mt < 2; ++mt)
#pragma unroll
                for (int nt = 0; nt < 8; ++nt)
                    MMA_TF32(acc[mt][nt], a[mt], b[nt]);
        }
    }

    // ---- epilogue ----
#pragma unroll
    for (int mt = 0; mt < 2; ++mt) {
        const int r0 = m0 + wm * 32 + mt * 16 + gid;
#pragma unroll
        for (int nt = 0; nt < 8; ++nt) {
            const int cl = wn * 64 + nt * 8 + 2 * tig;   // local col
            const float b0 = sbias[cl], b1 = sbias[cl + 1];
            if (r0 < n) {
                float2 v = make_float2(acc[mt][nt][0] + b0, acc[mt][nt][1] + b1);
                *(float2*)(out + (size_t)r0 * FEAT + by * 128 + cl) = v;
            }
            if (r0 + 8 < n) {
                float2 v = make_float2(acc[mt][nt][2] + b0, acc[mt][nt][3] + b1);
                *(float2*)(out + (size_t)(r0 + 8) * FEAT + by * 128 + cl) = v;
            }
        }
    }
}

// ---------------------------------------------------------------------------
extern "C" void kernel_launch(void* const* d_in, const int* in_sizes, int n_in,
                              void* d_out, int out_size) {
    const float* x      = (const float*)d_in[0];
    const void*  ei     = d_in[1];
    const float* Wsrel  = (const float*)d_in[2];
    const float* Wsroot = (const float*)d_in[3];
    const float* bs     = (const float*)d_in[4];
    const float* Wvrel  = (const float*)d_in[5];
    const float* Wvroot = (const float*)d_in[6];
    float*       out    = (float*)d_out;

    const int n = in_sizes[0] / FEAT;        // 10000
    const int E = in_sizes[1] / 2;           // 160000

    // Phase 0
    const int n4 = n * FEAT / 4;
    zero_kernel<<<(n4 + 255) / 256, 256>>>(n4);
    detect_kernel<<<1, 64>>>((const long long*)ei, (long long)n);

    // Phase 1
    const int blocks = (E * 32 + 255) / 256;
    scatter_kernel<<<blocks, 256>>>(x, ei, E);

    // Phase 2 (tf32 mma.sync)
    dim3 grid((n + 127) / 128, 4);
    mma_gemm_kernel<<<grid, 256>>>(x, Wsrel, Wsroot, bs, Wvrel, Wvroot, out, n);
}